// round 2
// baseline (speedup 1.0000x reference)
#include <cuda_runtime.h>
#include <cuda_bf16.h>
#include <math.h>

#define Bsz 512
#define Lq  196
#define Cc  384
#define NHh 12
#define HD  32
#define BH  (Bsz*NHh)      // 6144
#define MT  (Bsz*Lq)       // 100352
#define NQKV (3*Cc)        // 1152
#define QSCALE 0.17677669529663687f  // 32^-0.5

// ---------------- scratch (static device globals; no allocation) ----------------
__device__ float g_q[(size_t)BH*Lq*HD];      // 154 MB each
__device__ float g_k[(size_t)BH*Lq*HD];
__device__ float g_v[(size_t)BH*Lq*HD];
__device__ float g_attnout[(size_t)MT*Cc];   // [B, L, C] pre-proj
__device__ float g_bias[NHh*Lq*Lq];          // expanded relative-position bias

// ---------------- kernel 0: expand bias table ----------------
__global__ void bias_expand(const float* __restrict__ bt, const int* __restrict__ ridx) {
    int i = blockIdx.x * 256 + threadIdx.x;
    if (i < Lq*Lq) {
        int r = ridx[i];
        #pragma unroll
        for (int h = 0; h < NHh; h++)
            g_bias[h*(Lq*Lq) + i] = bt[r*NHh + h];
    }
}

// ---------------- kernel 1: QKV GEMM (100352 x 1152 x 384) ----------------
// 128x128x16 tiles, 256 threads, 8x8 register tiles. Exact tiling, no bounds checks.
__global__ __launch_bounds__(256) void qkv_gemm(const float* __restrict__ x,
                                                const float* __restrict__ w,
                                                const float* __restrict__ bias) {
    __shared__ float As[16][128];  // [k][m]
    __shared__ float Bs[16][128];  // [k][n]
    const int m0 = blockIdx.y * 128;
    const int n0 = blockIdx.x * 128;
    const int tid = threadIdx.x;
    const int tx = tid & 15, ty = tid >> 4;

    float acc[8][8];
    #pragma unroll
    for (int i = 0; i < 8; i++)
        #pragma unroll
        for (int j = 0; j < 8; j++) acc[i][j] = 0.f;

    for (int k0 = 0; k0 < Cc; k0 += 16) {
        #pragma unroll
        for (int i = 0; i < 2; i++) {
            int e = tid + i*256;
            int row = e >> 2, kq = (e & 3) << 2;
            float4 v = *(const float4*)(x + (size_t)(m0+row)*Cc + k0 + kq);
            As[kq+0][row] = v.x; As[kq+1][row] = v.y;
            As[kq+2][row] = v.z; As[kq+3][row] = v.w;
        }
        #pragma unroll
        for (int i = 0; i < 2; i++) {
            int e = tid + i*256;
            int kr = e >> 5, nq = (e & 31) << 2;
            *(float4*)&Bs[kr][nq] = *(const float4*)(w + (size_t)(k0+kr)*NQKV + n0 + nq);
        }
        __syncthreads();
        #pragma unroll
        for (int k = 0; k < 16; k++) {
            float a[8], b[8];
            *(float4*)&a[0] = *(float4*)&As[k][ty<<2];
            *(float4*)&a[4] = *(float4*)&As[k][(ty<<2)+64];
            *(float4*)&b[0] = *(float4*)&Bs[k][tx<<2];
            *(float4*)&b[4] = *(float4*)&Bs[k][(tx<<2)+64];
            #pragma unroll
            for (int i = 0; i < 8; i++)
                #pragma unroll
                for (int j = 0; j < 8; j++)
                    acc[i][j] = fmaf(a[i], b[j], acc[i][j]);
        }
        __syncthreads();
    }

    // epilogue: scatter into q (scaled) / k / v, layout [(b*12+h), l, d]
    #pragma unroll
    for (int i = 0; i < 8; i++) {
        int m = m0 + (ty<<2) + ((i < 4) ? i : (i + 60));
        int bb = m / Lq, l = m - bb*Lq;
        #pragma unroll
        for (int jj = 0; jj < 2; jj++) {
            int n = n0 + (tx<<2) + jj*64;
            int s = n / Cc;
            int rem = n - s*Cc;
            int h = rem >> 5, d = rem & 31;
            float* dst = (s == 0) ? g_q : ((s == 1) ? g_k : g_v);
            float sc = (s == 0) ? QSCALE : 1.f;
            float4 o;
            o.x = (acc[i][jj*4+0] + bias[n+0]) * sc;
            o.y = (acc[i][jj*4+1] + bias[n+1]) * sc;
            o.z = (acc[i][jj*4+2] + bias[n+2]) * sc;
            o.w = (acc[i][jj*4+3] + bias[n+3]) * sc;
            *(float4*)(dst + ((size_t)(bb*NHh + h)*Lq + l)*HD + d) = o;
        }
    }
}

// ---------------- kernel 2: fused attention, one block per (b, h) ----------------
#define SSTR 200   // S row stride (196 + 4 pad)

#define QK_ROW(I, QC) \
    acc[I][0] = fmaf(qa.QC, kb.x, acc[I][0]); \
    acc[I][1] = fmaf(qa.QC, kb.y, acc[I][1]); \
    acc[I][2] = fmaf(qa.QC, kb.z, acc[I][2]); \
    acc[I][3] = fmaf(qa.QC, kb.w, acc[I][3]);

#define PV_STEP(PC, VR) \
    acc[i][0] = fmaf(p[i].PC, vv[VR].x, acc[i][0]); \
    acc[i][1] = fmaf(p[i].PC, vv[VR].y, acc[i][1]); \
    acc[i][2] = fmaf(p[i].PC, vv[VR].z, acc[i][2]); \
    acc[i][3] = fmaf(p[i].PC, vv[VR].w, acc[i][3]);

__global__ __launch_bounds__(512) void attn_kernel() {
    extern __shared__ float sm[];
    float* S      = sm;                      // [196][200]  = 39200 floats
    float* Qs     = sm + 39200;              // [32][200]   = 6400
    float* Ks     = sm + 45600;              // [32][200]   = 6400
    float* Vs     = sm + 39200;              // [196][36]   = 7056 (reuses Qs/Ks)
    float* rowinv = sm + 39200 + 7056;       // [196]

    const int bh  = blockIdx.x;              // b*12 + h
    const int h   = bh % NHh;
    const int tid = threadIdx.x;

    // load Q, K transposed into smem: [d][l]
    {
        const float* qg = g_q + (size_t)bh*Lq*HD;
        const float* kg = g_k + (size_t)bh*Lq*HD;
        for (int e = tid; e < Lq*8; e += 512) {
            int l = e >> 3, dq = (e & 7) << 2;
            float4 a = *(const float4*)(qg + l*HD + dq);
            Qs[(dq+0)*SSTR + l] = a.x; Qs[(dq+1)*SSTR + l] = a.y;
            Qs[(dq+2)*SSTR + l] = a.z; Qs[(dq+3)*SSTR + l] = a.w;
            float4 c = *(const float4*)(kg + l*HD + dq);
            Ks[(dq+0)*SSTR + l] = c.x; Ks[(dq+1)*SSTR + l] = c.y;
            Ks[(dq+2)*SSTR + l] = c.z; Ks[(dq+3)*SSTR + l] = c.w;
        }
    }
    __syncthreads();

    // S = Q K^T + bias   (49x49 4x4-tiles)
    {
        const float* bia = g_bias + h*(Lq*Lq);
        for (int t = tid; t < 49*49; t += 512) {
            int ti = t / 49, tj = t - ti*49;
            int q0 = ti << 2, c0 = tj << 2;
            float acc[4][4];
            #pragma unroll
            for (int i = 0; i < 4; i++)
                #pragma unroll
                for (int j = 0; j < 4; j++) acc[i][j] = 0.f;
            #pragma unroll
            for (int d = 0; d < HD; d++) {
                float4 qa = *(float4*)&Qs[d*SSTR + q0];
                float4 kb = *(float4*)&Ks[d*SSTR + c0];
                QK_ROW(0, x) QK_ROW(1, y) QK_ROW(2, z) QK_ROW(3, w)
            }
            #pragma unroll
            for (int i = 0; i < 4; i++) {
                float4 bv = *(const float4*)(bia + (q0+i)*Lq + c0);
                float4 o;
                o.x = acc[i][0] + bv.x; o.y = acc[i][1] + bv.y;
                o.z = acc[i][2] + bv.z; o.w = acc[i][3] + bv.w;
                *(float4*)&S[(q0+i)*SSTR + c0] = o;
            }
        }
    }
    __syncthreads();   // Qs/Ks dead from here

    // load V into reused region; softmax rows (normalization deferred to epilogue)
    {
        const float* vg = g_v + (size_t)bh*Lq*HD;
        for (int e = tid; e < Lq*8; e += 512) {
            int l = e >> 3, dq = (e & 7) << 2;
            *(float4*)&Vs[l*36 + dq] = *(const float4*)(vg + l*HD + dq);
        }
        int wid = tid >> 5, lane = tid & 31;
        for (int row = wid; row < Lq; row += 16) {
            float* Sr = S + row*SSTR;
            float mx = -1e30f;
            for (int j = lane; j < Lq; j += 32) mx = fmaxf(mx, Sr[j]);
            #pragma unroll
            for (int o = 16; o > 0; o >>= 1) mx = fmaxf(mx, __shfl_xor_sync(0xffffffffu, mx, o));
            float sum = 0.f;
            for (int j = lane; j < Lq; j += 32) {
                float p = __expf(Sr[j] - mx);
                Sr[j] = p;
                sum += p;
            }
            #pragma unroll
            for (int o = 16; o > 0; o >>= 1) sum += __shfl_xor_sync(0xffffffffu, sum, o);
            if (lane == 0) rowinv[row] = 1.f / sum;
        }
    }
    __syncthreads();

    // O = P V  (49x8 4x4-tiles, kk chunked by 4 for float4 smem loads)
    {
        const int b = bh / NHh;
        float* og = g_attnout + (size_t)b*Lq*Cc;
        for (int t = tid; t < 49*8; t += 512) {
            int ti = t >> 3, tj = t & 7;
            int q0 = ti << 2, d0 = tj << 2;
            float acc[4][4];
            #pragma unroll
            for (int i = 0; i < 4; i++)
                #pragma unroll
                for (int j = 0; j < 4; j++) acc[i][j] = 0.f;
            for (int kk0 = 0; kk0 < Lq; kk0 += 4) {
                float4 p[4], vv[4];
                #pragma unroll
                for (int i = 0; i < 4; i++) p[i]  = *(float4*)&S[(q0+i)*SSTR + kk0];
                #pragma unroll
                for (int r = 0; r < 4; r++) vv[r] = *(float4*)&Vs[(kk0+r)*36 + d0];
                #pragma unroll
                for (int i = 0; i < 4; i++) {
                    PV_STEP(x, 0) PV_STEP(y, 1) PV_STEP(z, 2) PV_STEP(w, 3)
                }
            }
            #pragma unroll
            for (int i = 0; i < 4; i++) {
                float inv = rowinv[q0+i];
                float4 o;
                o.x = acc[i][0]*inv; o.y = acc[i][1]*inv;
                o.z = acc[i][2]*inv; o.w = acc[i][3]*inv;
                *(float4*)(og + (size_t)(q0+i)*Cc + h*HD + d0) = o;
            }
        }
    }
}

// ---------------- kernel 3: output projection (100352 x 384 x 384) ----------------
__global__ __launch_bounds__(256) void proj_gemm(const float* __restrict__ w,
                                                 const float* __restrict__ bias,
                                                 float* __restrict__ out) {
    __shared__ float As[16][128];
    __shared__ float Bs[16][128];
    const int m0 = blockIdx.y * 128;
    const int n0 = blockIdx.x * 128;
    const int tid = threadIdx.x;
    const int tx = tid & 15, ty = tid >> 4;

    float acc[8][8];
    #pragma unroll
    for (int i = 0; i < 8; i++)
        #pragma unroll
        for (int j = 0; j < 8; j++) acc[i][j] = 0.f;

    const float* x = g_attnout;
    for (int k0 = 0; k0 < Cc; k0 += 16) {
        #pragma unroll
        for (int i = 0; i < 2; i++) {
            int e = tid + i*256;
            int row = e >> 2, kq = (e & 3) << 2;
            float4 v = *(const float4*)(x + (size_t)(m0+row)*Cc + k0 + kq);
            As[kq+0][row] = v.x; As[kq+1][row] = v.y;
            As[kq+2][row] = v.z; As[kq+3][row] = v.w;
        }
        #pragma unroll
        for (int i = 0; i < 2; i++) {
            int e = tid + i*256;
            int kr = e >> 5, nq = (e & 31) << 2;
            *(float4*)&Bs[kr][nq] = *(const float4*)(w + (size_t)(k0+kr)*Cc + n0 + nq);
        }
        __syncthreads();
        #pragma unroll
        for (int k = 0; k < 16; k++) {
            float a[8], b[8];
            *(float4*)&a[0] = *(float4*)&As[k][ty<<2];
            *(float4*)&a[4] = *(float4*)&As[k][(ty<<2)+64];
            *(float4*)&b[0] = *(float4*)&Bs[k][tx<<2];
            *(float4*)&b[4] = *(float4*)&Bs[k][(tx<<2)+64];
            #pragma unroll
            for (int i = 0; i < 8; i++)
                #pragma unroll
                for (int j = 0; j < 8; j++)
                    acc[i][j] = fmaf(a[i], b[j], acc[i][j]);
        }
        __syncthreads();
    }

    #pragma unroll
    for (int i = 0; i < 8; i++) {
        int m = m0 + (ty<<2) + ((i < 4) ? i : (i + 60));
        #pragma unroll
        for (int jj = 0; jj < 2; jj++) {
            int n = n0 + (tx<<2) + jj*64;
            float4 o;
            o.x = acc[i][jj*4+0] + bias[n+0];
            o.y = acc[i][jj*4+1] + bias[n+1];
            o.z = acc[i][jj*4+2] + bias[n+2];
            o.w = acc[i][jj*4+3] + bias[n+3];
            *(float4*)(out + (size_t)m*Cc + n) = o;
        }
    }
}

// ---------------- launch ----------------
extern "C" void kernel_launch(void* const* d_in, const int* in_sizes, int n_in,
                              void* d_out, int out_size) {
    const float* x          = (const float*)d_in[0];
    const float* qkv_w      = (const float*)d_in[1];
    const float* qkv_b      = (const float*)d_in[2];
    const float* proj_w     = (const float*)d_in[3];
    const float* proj_b     = (const float*)d_in[4];
    const float* bias_table = (const float*)d_in[5];
    const int*   rel_index  = (const int*)d_in[6];
    float* out = (float*)d_out;

    cudaFuncSetAttribute(attn_kernel, cudaFuncAttributeMaxDynamicSharedMemorySize, 208000);

    bias_expand<<<(Lq*Lq + 255)/256, 256>>>(bias_table, rel_index);
    qkv_gemm<<<dim3(NQKV/128, MT/128), 256>>>(x, qkv_w, qkv_b);
    attn_kernel<<<BH, 512, 208000>>>();
    proj_gemm<<<dim3(Cc/128, MT/128), 256>>>(proj_w, proj_b, out);
}